// round 16
// baseline (speedup 1.0000x reference)
#include <cuda_runtime.h>

// ---------------------------------------------------------------------------
// SO8 rotation gate:
//   A = theta - theta^T  (per 8x8 block)
//   R = expm(A) via scale(2^s)+Taylor(12)+repeated squaring (global max_s)
//   y[..., n, o] = sum_e x[..., n, e] * R[n, e, o]
// expm signals PDL; apply is PDL-launched, issues its cp.async prologue
// BEFORE griddepcontrol.wait, then streams through an 8-stage (pow-2)
// per-thread smem ring. Stream loop is split: branch-free main phase
// (always refill) + 8-iteration drain phase (empty commit_groups keep the
// wait_group retirement invariant exact).
// ---------------------------------------------------------------------------

#define NB_MAX 4096
#define STAGES 8     // pow-2: stage index = rr & 7; 8*256*16B = 32KB/CTA

// permuted R: column chunk c = n*2+h owns 8 float4s,
// g_Rp[(c*8 + k)*4 + c4] = R[n][e][h*4+c4] with k = (e + 4h) & 7
__device__ float g_Rp[NB_MAX * 64];
__device__ float g_R[NB_MAX * 64];      // fallback path only
__device__ float g_s[NB_MAX];           // fallback path only
__device__ unsigned g_maxbits;          // global max of s (float bits, s>=0)
__device__ unsigned g_count;            // CTA arrival counter (reset by k_apply)

__device__ __forceinline__ void cp16(void* smem_dst, const void* gmem_src) {
    unsigned s = (unsigned)__cvta_generic_to_shared(smem_dst);
    asm volatile("cp.async.cg.shared.global [%0], [%1], 16;"
                 :: "r"(s), "l"(gmem_src) : "memory");
}
#define CP_COMMIT()  asm volatile("cp.async.commit_group;" ::: "memory")
#define CP_WAIT7()   asm volatile("cp.async.wait_group 7;" ::: "memory")

// ---------------------------------------------------------------------------
// Fused: Taylor + grid-wide max(s) via atomic+spin + squaring + permute.
// SAFE ONLY when all CTAs co-resident (grid <= 128 on 148 SMs).
// ---------------------------------------------------------------------------
__global__ __launch_bounds__(256) void k_expm_fused(const float* __restrict__ theta, int nb) {
    if (threadIdx.x == 0)
        asm volatile("griddepcontrol.launch_dependents;" ::: "memory");

    __shared__ float As_sh[4][64];
    __shared__ float red[4][2];
    __shared__ float buf[4][2][64];
    __shared__ float smax;

    int sub = threadIdx.x >> 6;
    int t   = threadIdx.x & 63;
    int i = t >> 3, j = t & 7;
    int n  = blockIdx.x * 4 + sub;
    int nc = min(n, nb - 1);           // clamp: inactive threads stay uniform

    float a = theta[nc * 64 + i * 8 + j] - theta[nc * 64 + j * 8 + i];

    float v = a * a;
    #pragma unroll
    for (int off = 16; off; off >>= 1) v += __shfl_down_sync(0xffffffffu, v, off);
    if ((threadIdx.x & 31) == 0) red[sub][(threadIdx.x >> 5) & 1] = v;
    __syncthreads();
    float norm = sqrtf(red[sub][0] + red[sub][1]);

    float s  = fmaxf(ceilf(log2f(norm + 1e-7f)), 0.0f);
    float as = a / (exp2f(s) + 1e-7f);

    As_sh[sub][t] = as;
    __syncthreads();
    float As_col[8];
    #pragma unroll
    for (int k = 0; k < 8; ++k) As_col[k] = As_sh[sub][k * 8 + j];

    float p = as;
    float r = (i == j ? 1.0f : 0.0f) + as;
    float fact = 1.0f;
    int   base = (i & 3) * 8;

    #pragma unroll
    for (int it = 2; it <= 12; ++it) {
        fact *= (float)it;
        float acc = 0.0f;
        #pragma unroll
        for (int k = 0; k < 8; ++k)
            acc = fmaf(__shfl_sync(0xffffffffu, p, base + k), As_col[k], acc);
        r += acc / fact;
        p  = acc;
    }

    buf[sub][0][t] = r;

    if (t == 0 && n < nb) atomicMax(&g_maxbits, __float_as_uint(s));
    __syncthreads();

    if (threadIdx.x == 0) {
        __threadfence();
        atomicAdd(&g_count, 1u);
        while (*(volatile unsigned*)&g_count != gridDim.x) { }
        __threadfence();
        smax = __uint_as_float(*(volatile unsigned*)&g_maxbits);
    }
    __syncthreads();
    float max_s = smax;

    int cur = 0;
    for (int k = 0; k < 8; ++k) {
        if ((float)k < max_s) {
            float acc = 0.0f;
            #pragma unroll
            for (int e = 0; e < 8; ++e)
                acc += buf[sub][cur][i * 8 + e] * buf[sub][cur][e * 8 + j];
            buf[sub][cur ^ 1][t] = acc;
            __syncthreads();
            cur ^= 1;
        }
    }

    if (n < nb) {
        float val = buf[sub][cur][t];
        int h  = j >> 2;
        int kk = (i + 4 * h) & 7;
        int c4 = j & 3;
        g_Rp[(((n * 2 + h) * 8) + kk) * 4 + c4] = val;
    }
}

// ------------------------- fallback pair (grid > 128) -----------------------
__global__ __launch_bounds__(256) void k_taylor(const float* __restrict__ theta, int nb) {
    __shared__ float As_sh[4][64];
    __shared__ float red[4][2];
    int sub = threadIdx.x >> 6;
    int t   = threadIdx.x & 63;
    int i = t >> 3, j = t & 7;
    int n  = blockIdx.x * 4 + sub;
    int nc = min(n, nb - 1);

    float a = theta[nc * 64 + i * 8 + j] - theta[nc * 64 + j * 8 + i];
    float v = a * a;
    #pragma unroll
    for (int off = 16; off; off >>= 1) v += __shfl_down_sync(0xffffffffu, v, off);
    if ((threadIdx.x & 31) == 0) red[sub][(threadIdx.x >> 5) & 1] = v;
    __syncthreads();
    float norm = sqrtf(red[sub][0] + red[sub][1]);
    float s  = fmaxf(ceilf(log2f(norm + 1e-7f)), 0.0f);
    float as = a / (exp2f(s) + 1e-7f);

    As_sh[sub][t] = as;
    __syncthreads();
    float As_col[8];
    #pragma unroll
    for (int k = 0; k < 8; ++k) As_col[k] = As_sh[sub][k * 8 + j];

    float p = as, fact = 1.0f;
    float r = (i == j ? 1.0f : 0.0f) + as;
    int   base = (i & 3) * 8;
    #pragma unroll
    for (int it = 2; it <= 12; ++it) {
        fact *= (float)it;
        float acc = 0.0f;
        #pragma unroll
        for (int k = 0; k < 8; ++k)
            acc = fmaf(__shfl_sync(0xffffffffu, p, base + k), As_col[k], acc);
        r += acc / fact;
        p  = acc;
    }
    if (n < nb) {
        g_R[n * 64 + t] = r;
        if (t == 0) g_s[n] = s;
    }
}

__global__ __launch_bounds__(256) void k_square(int nb) {
    __shared__ float buf[4][2][64];
    __shared__ float redm[8];
    int sub = threadIdx.x >> 6;
    int t   = threadIdx.x & 63;
    int i = t >> 3, j = t & 7;
    int n  = blockIdx.x * 4 + sub;
    int nc = min(n, nb - 1);

    float m = 0.0f;
    for (int k = threadIdx.x; k < nb; k += 256) m = fmaxf(m, g_s[k]);
    #pragma unroll
    for (int off = 16; off; off >>= 1)
        m = fmaxf(m, __shfl_down_sync(0xffffffffu, m, off));
    if ((threadIdx.x & 31) == 0) redm[threadIdx.x >> 5] = m;
    __syncthreads();
    float max_s = redm[0];
    #pragma unroll
    for (int w = 1; w < 8; ++w) max_s = fmaxf(max_s, redm[w]);

    buf[sub][0][t] = g_R[nc * 64 + t];
    __syncthreads();
    int cur = 0;
    for (int k = 0; k < 8; ++k) {
        if ((float)k < max_s) {
            float acc = 0.0f;
            #pragma unroll
            for (int e = 0; e < 8; ++e)
                acc += buf[sub][cur][i * 8 + e] * buf[sub][cur][e * 8 + j];
            buf[sub][cur ^ 1][t] = acc;
            __syncthreads();
            cur ^= 1;
        }
    }
    if (n < nb) {
        float val = buf[sub][cur][t];
        int h  = j >> 2;
        int kk = (i + 4 * h) & 7;
        int c4 = j & 3;
        g_Rp[(((n * 2 + h) * 8) + kk) * 4 + c4] = val;
    }
}

// ---------------------------------------------------------------------------
// K3: cp.async-pipelined apply, 8-stage pow-2 per-thread 16B slot ring.
// Split stream loop: main phase always refills (branch-free hot loop);
// drain phase commits EMPTY groups so 8 groups stay pending before every
// wait_group 7 -> the oldest group is always retired exactly when needed.
// No __syncthreads (each thread reads only its own slots). Prologue issued
// BEFORE griddepcontrol.wait so 8 rows of loads overlap the expm grid.
// ---------------------------------------------------------------------------
__global__ __launch_bounds__(256, 4) void k_apply(const float4* __restrict__ x,
                                                  float4* __restrict__ y,
                                                  int cols, int rows, int rpc) {
    __shared__ float4 xs[STAGES][256];
    int tid = threadIdx.x;
    int c = blockIdx.x * 256 + tid;           // column in float4 units
    long row0 = (long)blockIdx.y * rpc;
    int  nr   = (int)min((long)rpc, (long)rows - row0);
    long idx  = row0 * (long)cols + c;
    bool active = (c < cols);

    // pipeline prologue: x loads don't depend on expm -> issue before wait
    if (active) {
        #pragma unroll
        for (int s = 0; s < STAGES; ++s) {
            if (s < nr) cp16(&xs[s][tid], (const void*)(x + idx + (long)s * cols));
            CP_COMMIT();
        }
    }

    // wait for the expm grid (g_Rp producer) to fully complete
    asm volatile("griddepcontrol.wait;" ::: "memory");

    if (blockIdx.x == 0 && blockIdx.y == 0 && tid == 0) {
        g_count   = 0u;
        g_maxbits = 0u;
    }
    if (!active) return;

    float r[32];
    const float4* Rp = reinterpret_cast<const float4*>(g_Rp) + (long)c * 8;
    #pragma unroll
    for (int q = 0; q < 8; ++q) {
        float4 v = Rp[q];
        r[q * 4 + 0] = v.x; r[q * 4 + 1] = v.y;
        r[q * 4 + 2] = v.z; r[q * 4 + 3] = v.w;
    }

    int nmain = nr > STAGES ? nr - STAGES : 0;
    int rr = 0;

    // main phase: branch-free, refill every iteration
    for (; rr < nmain; ++rr, idx += cols) {
        CP_WAIT7();                            // group rr complete
        float4 v = xs[rr & (STAGES - 1)][tid];
        float z4 = __shfl_xor_sync(0xffffffffu, v.x, 1);
        float z5 = __shfl_xor_sync(0xffffffffu, v.y, 1);
        float z6 = __shfl_xor_sync(0xffffffffu, v.z, 1);
        float z7 = __shfl_xor_sync(0xffffffffu, v.w, 1);

        cp16(&xs[rr & (STAGES - 1)][tid],
             (const void*)(x + idx + (long)STAGES * cols));
        CP_COMMIT();

        float4 o;
        o.x = fmaf(z7, r[28], fmaf(z6, r[24], fmaf(z5, r[20], fmaf(z4, r[16],
              fmaf(v.w, r[12], fmaf(v.z, r[8],  fmaf(v.y, r[4],  v.x * r[0])))))));
        o.y = fmaf(z7, r[29], fmaf(z6, r[25], fmaf(z5, r[21], fmaf(z4, r[17],
              fmaf(v.w, r[13], fmaf(v.z, r[9],  fmaf(v.y, r[5],  v.x * r[1])))))));
        o.z = fmaf(z7, r[30], fmaf(z6, r[26], fmaf(z5, r[22], fmaf(z4, r[18],
              fmaf(v.w, r[14], fmaf(v.z, r[10], fmaf(v.y, r[6],  v.x * r[2])))))));
        o.w = fmaf(z7, r[31], fmaf(z6, r[27], fmaf(z5, r[23], fmaf(z4, r[19],
              fmaf(v.w, r[15], fmaf(v.z, r[11], fmaf(v.y, r[7],  v.x * r[3])))))));
        y[idx] = o;
    }

    // drain phase: empty commits keep 8 groups pending before each wait
    for (; rr < nr; ++rr, idx += cols) {
        CP_WAIT7();
        float4 v = xs[rr & (STAGES - 1)][tid];
        CP_COMMIT();                           // empty group: count alignment
        float z4 = __shfl_xor_sync(0xffffffffu, v.x, 1);
        float z5 = __shfl_xor_sync(0xffffffffu, v.y, 1);
        float z6 = __shfl_xor_sync(0xffffffffu, v.z, 1);
        float z7 = __shfl_xor_sync(0xffffffffu, v.w, 1);
        float4 o;
        o.x = fmaf(z7, r[28], fmaf(z6, r[24], fmaf(z5, r[20], fmaf(z4, r[16],
              fmaf(v.w, r[12], fmaf(v.z, r[8],  fmaf(v.y, r[4],  v.x * r[0])))))));
        o.y = fmaf(z7, r[29], fmaf(z6, r[25], fmaf(z5, r[21], fmaf(z4, r[17],
              fmaf(v.w, r[13], fmaf(v.z, r[9],  fmaf(v.y, r[5],  v.x * r[1])))))));
        o.z = fmaf(z7, r[30], fmaf(z6, r[26], fmaf(z5, r[22], fmaf(z4, r[18],
              fmaf(v.w, r[14], fmaf(v.z, r[10], fmaf(v.y, r[6],  v.x * r[2])))))));
        o.w = fmaf(z7, r[31], fmaf(z6, r[27], fmaf(z5, r[23], fmaf(z4, r[19],
              fmaf(v.w, r[15], fmaf(v.z, r[11], fmaf(v.y, r[7],  v.x * r[3])))))));
        y[idx] = o;
    }
}

extern "C" void kernel_launch(void* const* d_in, const int* in_sizes, int n_in,
                              void* d_out, int out_size) {
    const float* x     = (const float*)d_in[0];
    const float* theta = (const float*)d_in[1];
    float* out         = (float*)d_out;

    int  nb    = in_sizes[1] / 64;               // number of 8x8 blocks
    long total = (long)in_sizes[0];
    int  rows  = (int)(total / ((long)nb * 8));  // B*T

    int cols = nb * 2;                           // float4 columns per row
    int rpc  = 64;                               // rows per CTA (sweet spot)
    dim3 grid((cols + 255) / 256, (rows + rpc - 1) / rpc);

    // allow full smem carveout so 4 CTAs x 32KB stay resident per SM
    static int carveout_set = 0;
    if (!carveout_set) {
        cudaFuncSetAttribute(k_apply,
                             cudaFuncAttributePreferredSharedMemoryCarveout, 100);
        carveout_set = 1;
    }

    int gsetup = (nb + 3) / 4;
    if (gsetup <= 128) {
        k_expm_fused<<<gsetup, 256>>>(theta, nb);

        cudaLaunchConfig_t cfg = {};
        cfg.gridDim  = grid;
        cfg.blockDim = dim3(256, 1, 1);
        cfg.dynamicSmemBytes = 0;
        cfg.stream = 0;
        cudaLaunchAttribute attr[1];
        attr[0].id = cudaLaunchAttributeProgrammaticStreamSerialization;
        attr[0].val.programmaticStreamSerializationAllowed = 1;
        cfg.attrs = attr;
        cfg.numAttrs = 1;
        cudaError_t err = cudaLaunchKernelEx(&cfg, k_apply,
                                             (const float4*)x, (float4*)out,
                                             cols, rows, rpc);
        if (err != cudaSuccess) {
            k_apply<<<grid, 256>>>((const float4*)x, (float4*)out, cols, rows, rpc);
        }
    } else {
        k_taylor<<<gsetup, 256>>>(theta, nb);
        k_square<<<gsetup, 256>>>(nb);
        k_apply<<<grid, 256>>>((const float4*)x, (float4*)out, cols, rows, rpc);
    }
}

// round 17
// speedup vs baseline: 1.0155x; 1.0155x over previous
#include <cuda_runtime.h>

// ---------------------------------------------------------------------------
// SO8 rotation gate:
//   A = theta - theta^T  (per 8x8 block)
//   R = expm(A) via scale(2^s)+Taylor(12)+repeated squaring (global max_s)
//   y[..., n, o] = sum_e x[..., n, e] * R[n, e, o]
// expm signals PDL; apply is PDL-launched, issues a 12-deep cp.async prologue
// BEFORE griddepcontrol.wait (12 rows of x overlap the expm grid), then
// streams with a branch-free main loop (always refill) + drain loop (empty
// commits keep the wait_group retirement invariant exact). Stage indexing
// via cheap wrap counter.
// ---------------------------------------------------------------------------

#define NB_MAX 4096
#define STAGES 12    // 12 * 256 * 16B = 48KB/CTA; 4 CTAs = 192KB <= 228KB/SM

// permuted R: column chunk c = n*2+h owns 8 float4s,
// g_Rp[(c*8 + k)*4 + c4] = R[n][e][h*4+c4] with k = (e + 4h) & 7
__device__ float g_Rp[NB_MAX * 64];
__device__ float g_R[NB_MAX * 64];      // fallback path only
__device__ float g_s[NB_MAX];           // fallback path only
__device__ unsigned g_maxbits;          // global max of s (float bits, s>=0)
__device__ unsigned g_count;            // CTA arrival counter (reset by k_apply)

__device__ __forceinline__ void cp16(void* smem_dst, const void* gmem_src) {
    unsigned s = (unsigned)__cvta_generic_to_shared(smem_dst);
    asm volatile("cp.async.cg.shared.global [%0], [%1], 16;"
                 :: "r"(s), "l"(gmem_src) : "memory");
}
#define CP_COMMIT()  asm volatile("cp.async.commit_group;" ::: "memory")
#define CP_WAIT()    asm volatile("cp.async.wait_group %0;" :: "n"(STAGES - 1) : "memory")

// ---------------------------------------------------------------------------
// Fused: Taylor + grid-wide max(s) via atomic+spin + squaring + permute.
// SAFE ONLY when all CTAs co-resident (grid <= 128 on 148 SMs).
// ---------------------------------------------------------------------------
__global__ __launch_bounds__(256) void k_expm_fused(const float* __restrict__ theta, int nb) {
    if (threadIdx.x == 0)
        asm volatile("griddepcontrol.launch_dependents;" ::: "memory");

    __shared__ float As_sh[4][64];
    __shared__ float red[4][2];
    __shared__ float buf[4][2][64];
    __shared__ float smax;

    int sub = threadIdx.x >> 6;
    int t   = threadIdx.x & 63;
    int i = t >> 3, j = t & 7;
    int n  = blockIdx.x * 4 + sub;
    int nc = min(n, nb - 1);           // clamp: inactive threads stay uniform

    float a = theta[nc * 64 + i * 8 + j] - theta[nc * 64 + j * 8 + i];

    float v = a * a;
    #pragma unroll
    for (int off = 16; off; off >>= 1) v += __shfl_down_sync(0xffffffffu, v, off);
    if ((threadIdx.x & 31) == 0) red[sub][(threadIdx.x >> 5) & 1] = v;
    __syncthreads();
    float norm = sqrtf(red[sub][0] + red[sub][1]);

    float s  = fmaxf(ceilf(log2f(norm + 1e-7f)), 0.0f);
    float as = a / (exp2f(s) + 1e-7f);

    As_sh[sub][t] = as;
    __syncthreads();
    float As_col[8];
    #pragma unroll
    for (int k = 0; k < 8; ++k) As_col[k] = As_sh[sub][k * 8 + j];

    float p = as;
    float r = (i == j ? 1.0f : 0.0f) + as;
    float fact = 1.0f;
    int   base = (i & 3) * 8;

    #pragma unroll
    for (int it = 2; it <= 12; ++it) {
        fact *= (float)it;
        float acc = 0.0f;
        #pragma unroll
        for (int k = 0; k < 8; ++k)
            acc = fmaf(__shfl_sync(0xffffffffu, p, base + k), As_col[k], acc);
        r += acc / fact;
        p  = acc;
    }

    buf[sub][0][t] = r;

    if (t == 0 && n < nb) atomicMax(&g_maxbits, __float_as_uint(s));
    __syncthreads();

    if (threadIdx.x == 0) {
        __threadfence();
        atomicAdd(&g_count, 1u);
        while (*(volatile unsigned*)&g_count != gridDim.x) { }
        __threadfence();
        smax = __uint_as_float(*(volatile unsigned*)&g_maxbits);
    }
    __syncthreads();
    float max_s = smax;

    int cur = 0;
    for (int k = 0; k < 8; ++k) {
        if ((float)k < max_s) {
            float acc = 0.0f;
            #pragma unroll
            for (int e = 0; e < 8; ++e)
                acc += buf[sub][cur][i * 8 + e] * buf[sub][cur][e * 8 + j];
            buf[sub][cur ^ 1][t] = acc;
            __syncthreads();
            cur ^= 1;
        }
    }

    if (n < nb) {
        float val = buf[sub][cur][t];
        int h  = j >> 2;
        int kk = (i + 4 * h) & 7;
        int c4 = j & 3;
        g_Rp[(((n * 2 + h) * 8) + kk) * 4 + c4] = val;
    }
}

// ------------------------- fallback pair (grid > 128) -----------------------
__global__ __launch_bounds__(256) void k_taylor(const float* __restrict__ theta, int nb) {
    __shared__ float As_sh[4][64];
    __shared__ float red[4][2];
    int sub = threadIdx.x >> 6;
    int t   = threadIdx.x & 63;
    int i = t >> 3, j = t & 7;
    int n  = blockIdx.x * 4 + sub;
    int nc = min(n, nb - 1);

    float a = theta[nc * 64 + i * 8 + j] - theta[nc * 64 + j * 8 + i];
    float v = a * a;
    #pragma unroll
    for (int off = 16; off; off >>= 1) v += __shfl_down_sync(0xffffffffu, v, off);
    if ((threadIdx.x & 31) == 0) red[sub][(threadIdx.x >> 5) & 1] = v;
    __syncthreads();
    float norm = sqrtf(red[sub][0] + red[sub][1]);
    float s  = fmaxf(ceilf(log2f(norm + 1e-7f)), 0.0f);
    float as = a / (exp2f(s) + 1e-7f);

    As_sh[sub][t] = as;
    __syncthreads();
    float As_col[8];
    #pragma unroll
    for (int k = 0; k < 8; ++k) As_col[k] = As_sh[sub][k * 8 + j];

    float p = as, fact = 1.0f;
    float r = (i == j ? 1.0f : 0.0f) + as;
    int   base = (i & 3) * 8;
    #pragma unroll
    for (int it = 2; it <= 12; ++it) {
        fact *= (float)it;
        float acc = 0.0f;
        #pragma unroll
        for (int k = 0; k < 8; ++k)
            acc = fmaf(__shfl_sync(0xffffffffu, p, base + k), As_col[k], acc);
        r += acc / fact;
        p  = acc;
    }
    if (n < nb) {
        g_R[n * 64 + t] = r;
        if (t == 0) g_s[n] = s;
    }
}

__global__ __launch_bounds__(256) void k_square(int nb) {
    __shared__ float buf[4][2][64];
    __shared__ float redm[8];
    int sub = threadIdx.x >> 6;
    int t   = threadIdx.x & 63;
    int i = t >> 3, j = t & 7;
    int n  = blockIdx.x * 4 + sub;
    int nc = min(n, nb - 1);

    float m = 0.0f;
    for (int k = threadIdx.x; k < nb; k += 256) m = fmaxf(m, g_s[k]);
    #pragma unroll
    for (int off = 16; off; off >>= 1)
        m = fmaxf(m, __shfl_down_sync(0xffffffffu, m, off));
    if ((threadIdx.x & 31) == 0) redm[threadIdx.x >> 5] = m;
    __syncthreads();
    float max_s = redm[0];
    #pragma unroll
    for (int w = 1; w < 8; ++w) max_s = fmaxf(max_s, redm[w]);

    buf[sub][0][t] = g_R[nc * 64 + t];
    __syncthreads();
    int cur = 0;
    for (int k = 0; k < 8; ++k) {
        if ((float)k < max_s) {
            float acc = 0.0f;
            #pragma unroll
            for (int e = 0; e < 8; ++e)
                acc += buf[sub][cur][i * 8 + e] * buf[sub][cur][e * 8 + j];
            buf[sub][cur ^ 1][t] = acc;
            __syncthreads();
            cur ^= 1;
        }
    }
    if (n < nb) {
        float val = buf[sub][cur][t];
        int h  = j >> 2;
        int kk = (i + 4 * h) & 7;
        int c4 = j & 3;
        g_Rp[(((n * 2 + h) * 8) + kk) * 4 + c4] = val;
    }
}

// ---------------------------------------------------------------------------
// K3: cp.async-pipelined apply, 12-stage per-thread 16B slot ring with cheap
// wrap-counter indexing. Branch-free main loop (always refill) + drain loop
// (empty commits keep 12 groups pending before every wait_group 11).
// No __syncthreads (each thread reads only its own slots). Prologue issued
// BEFORE griddepcontrol.wait so 12 rows of loads overlap the expm grid.
// ---------------------------------------------------------------------------
__global__ __launch_bounds__(256, 4) void k_apply(const float4* __restrict__ x,
                                                  float4* __restrict__ y,
                                                  int cols, int rows, int rpc) {
    __shared__ float4 xs[STAGES][256];
    int tid = threadIdx.x;
    int c = blockIdx.x * 256 + tid;           // column in float4 units
    long row0 = (long)blockIdx.y * rpc;
    int  nr   = (int)min((long)rpc, (long)rows - row0);
    long idx  = row0 * (long)cols + c;
    bool active = (c < cols);

    // pipeline prologue: x loads don't depend on expm -> issue before wait
    if (active) {
        #pragma unroll
        for (int s = 0; s < STAGES; ++s) {
            if (s < nr) cp16(&xs[s][tid], (const void*)(x + idx + (long)s * cols));
            CP_COMMIT();
        }
    }

    // wait for the expm grid (g_Rp producer) to fully complete
    asm volatile("griddepcontrol.wait;" ::: "memory");

    if (blockIdx.x == 0 && blockIdx.y == 0 && tid == 0) {
        g_count   = 0u;
        g_maxbits = 0u;
    }
    if (!active) return;

    float r[32];
    const float4* Rp = reinterpret_cast<const float4*>(g_Rp) + (long)c * 8;
    #pragma unroll
    for (int q = 0; q < 8; ++q) {
        float4 v = Rp[q];
        r[q * 4 + 0] = v.x; r[q * 4 + 1] = v.y;
        r[q * 4 + 2] = v.z; r[q * 4 + 3] = v.w;
    }

    int nmain = nr > STAGES ? nr - STAGES : 0;
    int rr = 0;
    int stage = 0;

    // main phase: branch-free, refill every iteration
    for (; rr < nmain; ++rr, idx += cols) {
        CP_WAIT();                             // oldest group complete
        float4 v = xs[stage][tid];
        float z4 = __shfl_xor_sync(0xffffffffu, v.x, 1);
        float z5 = __shfl_xor_sync(0xffffffffu, v.y, 1);
        float z6 = __shfl_xor_sync(0xffffffffu, v.z, 1);
        float z7 = __shfl_xor_sync(0xffffffffu, v.w, 1);

        cp16(&xs[stage][tid], (const void*)(x + idx + (long)STAGES * cols));
        CP_COMMIT();
        if (++stage == STAGES) stage = 0;

        float4 o;
        o.x = fmaf(z7, r[28], fmaf(z6, r[24], fmaf(z5, r[20], fmaf(z4, r[16],
              fmaf(v.w, r[12], fmaf(v.z, r[8],  fmaf(v.y, r[4],  v.x * r[0])))))));
        o.y = fmaf(z7, r[29], fmaf(z6, r[25], fmaf(z5, r[21], fmaf(z4, r[17],
              fmaf(v.w, r[13], fmaf(v.z, r[9],  fmaf(v.y, r[5],  v.x * r[1])))))));
        o.z = fmaf(z7, r[30], fmaf(z6, r[26], fmaf(z5, r[22], fmaf(z4, r[18],
              fmaf(v.w, r[14], fmaf(v.z, r[10], fmaf(v.y, r[6],  v.x * r[2])))))));
        o.w = fmaf(z7, r[31], fmaf(z6, r[27], fmaf(z5, r[23], fmaf(z4, r[19],
              fmaf(v.w, r[15], fmaf(v.z, r[11], fmaf(v.y, r[7],  v.x * r[3])))))));
        y[idx] = o;
    }

    // drain phase: empty commits keep STAGES groups pending before each wait
    for (; rr < nr; ++rr, idx += cols) {
        CP_WAIT();
        float4 v = xs[stage][tid];
        CP_COMMIT();                           // empty group: count alignment
        if (++stage == STAGES) stage = 0;
        float z4 = __shfl_xor_sync(0xffffffffu, v.x, 1);
        float z5 = __shfl_xor_sync(0xffffffffu, v.y, 1);
        float z6 = __shfl_xor_sync(0xffffffffu, v.z, 1);
        float z7 = __shfl_xor_sync(0xffffffffu, v.w, 1);
        float4 o;
        o.x = fmaf(z7, r[28], fmaf(z6, r[24], fmaf(z5, r[20], fmaf(z4, r[16],
              fmaf(v.w, r[12], fmaf(v.z, r[8],  fmaf(v.y, r[4],  v.x * r[0])))))));
        o.y = fmaf(z7, r[29], fmaf(z6, r[25], fmaf(z5, r[21], fmaf(z4, r[17],
              fmaf(v.w, r[13], fmaf(v.z, r[9],  fmaf(v.y, r[5],  v.x * r[1])))))));
        o.z = fmaf(z7, r[30], fmaf(z6, r[26], fmaf(z5, r[22], fmaf(z4, r[18],
              fmaf(v.w, r[14], fmaf(v.z, r[10], fmaf(v.y, r[6],  v.x * r[2])))))));
        o.w = fmaf(z7, r[31], fmaf(z6, r[27], fmaf(z5, r[23], fmaf(z4, r[19],
              fmaf(v.w, r[15], fmaf(v.z, r[11], fmaf(v.y, r[7],  v.x * r[3])))))));
        y[idx] = o;
    }
}

extern "C" void kernel_launch(void* const* d_in, const int* in_sizes, int n_in,
                              void* d_out, int out_size) {
    const float* x     = (const float*)d_in[0];
    const float* theta = (const float*)d_in[1];
    float* out         = (float*)d_out;

    int  nb    = in_sizes[1] / 64;               // number of 8x8 blocks
    long total = (long)in_sizes[0];
    int  rows  = (int)(total / ((long)nb * 8));  // B*T

    int cols = nb * 2;                           // float4 columns per row
    int rpc  = 64;                               // rows per CTA (sweet spot)
    dim3 grid((cols + 255) / 256, (rows + rpc - 1) / rpc);

    // allow full smem carveout so 4 CTAs x 48KB stay resident per SM
    static int carveout_set = 0;
    if (!carveout_set) {
        cudaFuncSetAttribute(k_apply,
                             cudaFuncAttributePreferredSharedMemoryCarveout, 100);
        carveout_set = 1;
    }

    int gsetup = (nb + 3) / 4;
    if (gsetup <= 128) {
        k_expm_fused<<<gsetup, 256>>>(theta, nb);

        cudaLaunchConfig_t cfg = {};
        cfg.gridDim  = grid;
        cfg.blockDim = dim3(256, 1, 1);
        cfg.dynamicSmemBytes = 0;
        cfg.stream = 0;
        cudaLaunchAttribute attr[1];
        attr[0].id = cudaLaunchAttributeProgrammaticStreamSerialization;
        attr[0].val.programmaticStreamSerializationAllowed = 1;
        cfg.attrs = attr;
        cfg.numAttrs = 1;
        cudaError_t err = cudaLaunchKernelEx(&cfg, k_apply,
                                             (const float4*)x, (float4*)out,
                                             cols, rows, rpc);
        if (err != cudaSuccess) {
            k_apply<<<grid, 256>>>((const float4*)x, (float4*)out, cols, rows, rpc);
        }
    } else {
        k_taylor<<<gsetup, 256>>>(theta, nb);
        k_square<<<gsetup, 256>>>(nb);
        k_apply<<<grid, 256>>>((const float4*)x, (float4*)out, cols, rows, rpc);
    }
}